// round 3
// baseline (speedup 1.0000x reference)
#include <cuda_runtime.h>
#include <cstddef>

#define WORDS   1000000
#define EMB_D   64
#define KTH     4
#define BATCH   8192

#define E_ELEMS   ((long)WORDS * EMB_D)          // 64,000,000
#define B_ELEMS   ((long)WORDS * KTH)            // 4,000,000
#define TOT_ELEMS (E_ELEMS + B_ELEMS)            // 68,000,000
#define K_CH      (TOT_ELEMS / 4)                // 17,000,000 float4 chunks
#define E_CH      (E_ELEMS / 4)                  // 16,000,000
#define RB        128                            // reduce blocks
#define INVB      (1.0f / (float)BATCH)

// Per-block partials (always fully overwritten each launch -> graph-replay safe).
__device__ float g_pw[RB][EMB_D];
__device__ float g_pb[RB][KTH];
__device__ int   g_pc[RB];

// ---------------------------------------------------------------------------
// Reduce: one warp per group of targets; per-block partials, no atomics.
// ---------------------------------------------------------------------------
__global__ void prank_reduce_kernel(const float* __restrict__ embed,
                                    const float* __restrict__ bias,
                                    const int*   __restrict__ ctx_id,
                                    const int*   __restrict__ tgt,
                                    const int*   __restrict__ lab) {
    __shared__ float s_ctx[EMB_D];
    __shared__ float s_bias[KTH];
    __shared__ float s_w[8][EMB_D];
    __shared__ float s_b[8][KTH];
    __shared__ int   s_c[8];

    const int tid = threadIdx.x;
    const int ctx = __ldg(ctx_id);
    if (tid < EMB_D) s_ctx[tid]  = __ldg(embed + (size_t)ctx * EMB_D + tid);
    if (tid < KTH)   s_bias[tid] = __ldg(bias  + (size_t)ctx * KTH + tid);
    __syncthreads();

    const int warp   = tid >> 5;
    const int lane   = tid & 31;
    const int nwarps = blockDim.x >> 5;
    const int gwarp  = blockIdx.x * nwarps + warp;
    const int twarps = gridDim.x * nwarps;

    const float2 c2 = reinterpret_cast<const float2*>(s_ctx)[lane];

    float wx = 0.0f, wy = 0.0f;
    float b0 = 0.0f, b1 = 0.0f, b2 = 0.0f, b3 = 0.0f;
    int corr = 0;

    for (int b = gwarp; b < BATCH; b += twarps) {
        const int t = __ldg(tgt + b);
        const float2 e2 =
            reinterpret_cast<const float2*>(embed + (size_t)t * EMB_D)[lane];
        float p = e2.x * c2.x + e2.y * c2.y;
        #pragma unroll
        for (int o = 16; o; o >>= 1) p += __shfl_xor_sync(0xffffffffu, p, o);
        const float dot = p;

        const int   L    = __ldg(lab + b);
        const float labf = (float)L;

        float taurow = 0.0f;
        int   plabel = KTH + 1;
        float tj[KTH];
        #pragma unroll
        for (int j = KTH - 1; j >= 0; j--) {
            const float db = dot - s_bias[j];
            if (db <= 0.0f) plabel = j + 1;
            const float yt  = (j < L) ? 1.0f : -1.0f;
            const float tau = (db * yt > 0.0f) ? 0.0f : labf;
            tj[j] = tau;
            taurow += tau;
        }
        if (lane == 0) {
            b0 += tj[0]; b1 += tj[1]; b2 += tj[2]; b3 += tj[3];
            if (plabel == L) corr++;
        }
        wx += taurow * e2.x;
        wy += taurow * e2.y;
    }

    s_w[warp][2 * lane]     = wx;
    s_w[warp][2 * lane + 1] = wy;
    if (lane == 0) {
        s_b[warp][0] = b0; s_b[warp][1] = b1; s_b[warp][2] = b2; s_b[warp][3] = b3;
        s_c[warp] = corr;
    }
    __syncthreads();

    if (tid < EMB_D) {
        float s = 0.0f;
        #pragma unroll
        for (int w = 0; w < 8; w++) s += s_w[w][tid];
        g_pw[blockIdx.x][tid] = s;
    }
    if (tid < KTH) {
        float s = 0.0f;
        #pragma unroll
        for (int w = 0; w < 8; w++) s += s_b[w][tid];
        g_pb[blockIdx.x][tid] = s;
    }
    if (tid == 0) {
        int s = 0;
        #pragma unroll
        for (int w = 0; w < 8; w++) s += s_c[w];
        g_pc[blockIdx.x] = s;
    }
}

// ---------------------------------------------------------------------------
// Copy + finalize (4 chunks = 64B per thread)
// ---------------------------------------------------------------------------
__device__ __forceinline__ float load_src(long s,
                                          const float* __restrict__ emb,
                                          const float* __restrict__ bia) {
    return (s < E_ELEMS) ? __ldg(emb + s) : __ldg(bia + (s - E_ELEMS));
}

__device__ __forceinline__ float4 load_chunk(long k,
                                             const float* __restrict__ emb,
                                             const float* __restrict__ bia) {
    const float4* p = (k < E_CH)
        ? (reinterpret_cast<const float4*>(emb) + k)
        : (reinterpret_cast<const float4*>(bia) + (k - E_CH));
    return __ldg(p);
}

__device__ __forceinline__ float sum_w(int t) {
    float s = 0.0f;
    #pragma unroll 8
    for (int b = 0; b < RB; b++) s += g_pw[b][t];
    return s;
}
__device__ __forceinline__ float sum_b(int t) {
    float s = 0.0f;
    #pragma unroll 8
    for (int b = 0; b < RB; b++) s += g_pb[b][t];
    return s;
}

// Thread t handles chunks 4t+1 .. 4t+4 (output out[16t+4 .. 16t+20)).
__global__ void __launch_bounds__(256)
prank_copy_finalize_kernel(const float* __restrict__ emb,
                           const float* __restrict__ bia,
                           const int*   __restrict__ ctx_id,
                           float* __restrict__ out) {
    const long t  = (long)blockIdx.x * blockDim.x + threadIdx.x;
    const long k0 = 4 * t + 1;                    // first chunk

    // Load 4 aligned float4 chunks (clamped for the last partial thread).
    float4 B[4];
    #pragma unroll
    for (int i = 0; i < 4; i++) {
        long k = k0 + i;
        if (k >= K_CH) k = K_CH - 1;
        B[i] = load_chunk(k, emb, bia);
    }

    // Leading element src[4*k0 - 1] = src[16t+3]:
    // previous thread's B[3].w; lane 0 does one scalar load.
    float prev = __shfl_up_sync(0xffffffffu, B[3].w, 1);
    if ((threadIdx.x & 31) == 0) prev = load_src(4 * k0 - 1, emb, bia);

    // Shifted output registers: o[4i..4i+3] = src[4(k0+i)-1 .. 4(k0+i)+2]
    float o[16];
    o[0] = prev;    o[1] = B[0].x;  o[2] = B[0].y;  o[3] = B[0].z;
    o[4] = B[0].w;  o[5] = B[1].x;  o[6] = B[1].y;  o[7] = B[1].z;
    o[8] = B[1].w;  o[9] = B[2].x;  o[10] = B[2].y; o[11] = B[2].z;
    o[12] = B[2].w; o[13] = B[3].x; o[14] = B[3].y; o[15] = B[3].z;

    // Patch the context row if this thread's 16-element source window overlaps.
    {
        const long s0    = 4 * k0 - 1;            // window [s0, s0+15]
        const int  ctx   = __ldg(ctx_id);
        const long wbase = (long)ctx * EMB_D;
        const long bbase = E_ELEMS + (long)ctx * KTH;

        if (s0 <= wbase + (EMB_D - 1) && s0 + 15 >= wbase) {
            #pragma unroll
            for (int c = 0; c < 16; c++) {
                const long idx = s0 + c;
                if (idx >= wbase && idx < wbase + EMB_D)
                    o[c] += sum_w((int)(idx - wbase)) * INVB;
            }
        }
        if (s0 + 15 >= bbase) {   // window end vs bias row start (bias is at the very top)
            #pragma unroll
            for (int c = 0; c < 16; c++) {
                const long idx = s0 + c;
                if (idx >= bbase && idx < bbase + KTH)
                    o[c] -= sum_b((int)(idx - bbase)) * INVB;
            }
        }
    }

    // Aligned float4 stores at out[4k], k = k0..k0+3.
    #pragma unroll
    for (int i = 0; i < 4; i++) {
        const long k = k0 + i;
        if (k < K_CH)
            reinterpret_cast<float4*>(out)[k] =
                make_float4(o[4 * i], o[4 * i + 1], o[4 * i + 2], o[4 * i + 3]);
    }

    if (t == 0) {
        const int  ctx   = __ldg(ctx_id);
        const long wbase = (long)ctx * EMB_D;
        const long bbase = E_ELEMS + (long)ctx * KTH;

        int c = 0;
        #pragma unroll 8
        for (int b = 0; b < RB; b++) c += g_pc[b];
        out[0] = (float)c * INVB;

        // Head: out[1..3] = src[0..2] (patched only if ctx == 0).
        #pragma unroll
        for (int j = 0; j < 3; j++) {
            float v = load_src(j, emb, bia);
            if (j >= wbase && j < wbase + EMB_D)
                v += sum_w(j - (int)wbase) * INVB;
            out[1 + j] = v;
        }
        // Tail: out[TOT] = src[TOT-1] (patched only if ctx == WORDS-1).
        {
            const long j = TOT_ELEMS - 1;
            float v = load_src(j, emb, bia);
            if (j >= bbase && j < bbase + KTH)
                v -= sum_b((int)(j - bbase)) * INVB;
            out[TOT_ELEMS] = v;
        }
    }
}

extern "C" void kernel_launch(void* const* d_in, const int* in_sizes, int n_in,
                              void* d_out, int out_size) {
    const float* in_embed = (const float*)d_in[0];
    const float* in_bias  = (const float*)d_in[1];
    const int*   ctx_id   = (const int*)d_in[2];
    const int*   tgt      = (const int*)d_in[3];
    const int*   lab      = (const int*)d_in[4];
    float* out = (float*)d_out;
    (void)n_in; (void)out_size; (void)in_sizes;

    prank_reduce_kernel<<<RB, 256>>>(in_embed, in_bias, ctx_id, tgt, lab);

    const long nthreads = (K_CH - 1 + 3) / 4;     // 4 chunks per thread
    const int  blocks   = (int)((nthreads + 255) / 256);
    prank_copy_finalize_kernel<<<blocks, 256>>>(in_embed, in_bias, ctx_id, out);
}

// round 7
// speedup vs baseline: 1.1914x; 1.1914x over previous
#include <cuda_runtime.h>
#include <cstddef>

#define WORDS   1000000
#define EMB_D   64
#define KTH     4
#define BATCH   8192

#define E_ELEMS   ((long)WORDS * EMB_D)          // 64,000,000
#define B_ELEMS   ((long)WORDS * KTH)            // 4,000,000
#define TOT_ELEMS (E_ELEMS + B_ELEMS)            // 68,000,000
#define K_CH      (TOT_ELEMS / 4)                // 17,000,000 float4 chunks
#define E_CH      (E_ELEMS / 4)                  // 16,000,000
#define RB        128                            // reduce blocks
#define INVB      (1.0f / (float)BATCH)

#define TPB     256
#define UNROLL  4
#define CPB     (TPB * UNROLL)                   // 1024 chunks per block

// Per-block partials (fully overwritten each launch -> graph-replay safe).
__device__ float g_pw[RB][EMB_D];
__device__ float g_pb[RB][KTH];
__device__ int   g_pc[RB];

// ---------------------------------------------------------------------------
// Helpers
// ---------------------------------------------------------------------------
__device__ __forceinline__ float load_src(long s,
                                          const float* __restrict__ emb,
                                          const float* __restrict__ bia) {
    return (s < E_ELEMS) ? __ldg(emb + s) : __ldg(bia + (s - E_ELEMS));
}

__device__ __forceinline__ float4 load_chunk_cs(long k,
                                                const float* __restrict__ emb,
                                                const float* __restrict__ bia) {
    const float4* p = (k < E_CH)
        ? (reinterpret_cast<const float4*>(emb) + k)
        : (reinterpret_cast<const float4*>(bia) + (k - E_CH));
    return __ldcs(p);
}

__device__ __forceinline__ float sum_w(int t) {
    float s = 0.0f;
    #pragma unroll 8
    for (int b = 0; b < RB; b++) s += g_pw[b][t];
    return s;
}
__device__ __forceinline__ float sum_b(int t) {
    float s = 0.0f;
    #pragma unroll 8
    for (int b = 0; b < RB; b++) s += g_pb[b][t];
    return s;
}

// ---------------------------------------------------------------------------
// Reduce body (runs inside copy kernel for blockIdx.x < RB)
// ---------------------------------------------------------------------------
__device__ void reduce_body(const float* __restrict__ embed,
                            const float* __restrict__ bias,
                            const int*   __restrict__ ctx_id,
                            const int*   __restrict__ tgt,
                            const int*   __restrict__ lab) {
    __shared__ float s_ctx[EMB_D];
    __shared__ float s_bias[KTH];
    __shared__ float s_w[8][EMB_D];
    __shared__ float s_b[8][KTH];
    __shared__ int   s_c[8];

    const int tid = threadIdx.x;
    const int ctx = __ldg(ctx_id);
    if (tid < EMB_D) s_ctx[tid]  = __ldg(embed + (size_t)ctx * EMB_D + tid);
    if (tid < KTH)   s_bias[tid] = __ldg(bias  + (size_t)ctx * KTH + tid);
    __syncthreads();

    const int warp  = tid >> 5;
    const int lane  = tid & 31;
    const int gwarp = blockIdx.x * 8 + warp;     // 1024 warps total
    const int twarps = RB * 8;

    const float2 c2 = reinterpret_cast<const float2*>(s_ctx)[lane];

    float wx = 0.0f, wy = 0.0f;
    float b0 = 0.0f, b1 = 0.0f, b2 = 0.0f, b3 = 0.0f;
    int corr = 0;

    for (int b = gwarp; b < BATCH; b += twarps) {
        const int t = __ldg(tgt + b);
        const float2 e2 =
            reinterpret_cast<const float2*>(embed + (size_t)t * EMB_D)[lane];
        float p = e2.x * c2.x + e2.y * c2.y;
        #pragma unroll
        for (int o = 16; o; o >>= 1) p += __shfl_xor_sync(0xffffffffu, p, o);
        const float dot = p;

        const int   L    = __ldg(lab + b);
        const float labf = (float)L;

        float taurow = 0.0f;
        int   plabel = KTH + 1;
        float tj[KTH];
        #pragma unroll
        for (int j = KTH - 1; j >= 0; j--) {
            const float db = dot - s_bias[j];
            if (db <= 0.0f) plabel = j + 1;
            const float yt  = (j < L) ? 1.0f : -1.0f;
            const float tau = (db * yt > 0.0f) ? 0.0f : labf;
            tj[j] = tau;
            taurow += tau;
        }
        if (lane == 0) {
            b0 += tj[0]; b1 += tj[1]; b2 += tj[2]; b3 += tj[3];
            if (plabel == L) corr++;
        }
        wx += taurow * e2.x;
        wy += taurow * e2.y;
    }

    s_w[warp][2 * lane]     = wx;
    s_w[warp][2 * lane + 1] = wy;
    if (lane == 0) {
        s_b[warp][0] = b0; s_b[warp][1] = b1; s_b[warp][2] = b2; s_b[warp][3] = b3;
        s_c[warp] = corr;
    }
    __syncthreads();

    if (tid < EMB_D) {
        float s = 0.0f;
        #pragma unroll
        for (int w = 0; w < 8; w++) s += s_w[w][tid];
        g_pw[blockIdx.x][tid] = s;
    }
    if (tid < KTH) {
        float s = 0.0f;
        #pragma unroll
        for (int w = 0; w < 8; w++) s += s_b[w][tid];
        g_pb[blockIdx.x][tid] = s;
    }
    if (tid == 0) {
        int s = 0;
        #pragma unroll
        for (int w = 0; w < 8; w++) s += s_c[w];
        g_pc[blockIdx.x] = s;
    }
}

// ---------------------------------------------------------------------------
// Fused kernel: blocks 0..RB-1 reduce first, then all blocks stream-copy.
// Pure shifted copy: out[4k .. 4k+3] = src[4k-1 .. 4k+2] for chunks k.
// Coalesced: thread tid of a block handles chunks base + i*TPB + tid.
// ---------------------------------------------------------------------------
__global__ void __launch_bounds__(TPB)
prank_main_kernel(const float* __restrict__ emb,
                  const float* __restrict__ bia,
                  const int*   __restrict__ ctx_id,
                  const int*   __restrict__ tgt,
                  const int*   __restrict__ lab,
                  float* __restrict__ out) {
    if (blockIdx.x < RB)
        reduce_body(emb, bia, ctx_id, tgt, lab);

    const long base = (long)blockIdx.x * CPB + 1;
    const int  tid  = threadIdx.x;
    const int  lane = tid & 31;

    long   k[UNROLL];
    float4 B[UNROLL];
    float  prev[UNROLL];

    #pragma unroll
    for (int i = 0; i < UNROLL; i++) {
        long kk = base + (long)i * TPB + tid;
        if (kk >= K_CH) kk = K_CH - 1;            // clamp keeps warp converged
        k[i] = kk;
        B[i] = load_chunk_cs(kk, emb, bia);
    }

    #pragma unroll
    for (int i = 0; i < UNROLL; i++) {
        prev[i] = __shfl_up_sync(0xffffffffu, B[i].w, 1);
        if (lane == 0) prev[i] = load_src(4 * k[i] - 1, emb, bia);
    }

    #pragma unroll
    for (int i = 0; i < UNROLL; i++) {
        const long kk = base + (long)i * TPB + tid;
        if (kk < K_CH) {
            __stcs(reinterpret_cast<float4*>(out) + kk,
                   make_float4(prev[i], B[i].x, B[i].y, B[i].z));
        }
    }
}

// ---------------------------------------------------------------------------
// Patch: fix the 68 context-row elements in-place, write acc, head, tail.
// ---------------------------------------------------------------------------
__global__ void prank_patch_kernel(const float* __restrict__ emb,
                                   const float* __restrict__ bia,
                                   const int*   __restrict__ ctx_id,
                                   float* __restrict__ out) {
    const int t   = threadIdx.x;
    const int ctx = __ldg(ctx_id);
    const long wbase = (long)ctx * EMB_D;
    const long bbase = E_ELEMS + (long)ctx * KTH;

    if (t == 64) {
        int c = 0;
        #pragma unroll 8
        for (int b = 0; b < RB; b++) c += g_pc[b];
        out[0] = (float)c * INVB;
    }

    // Embed-row patch (skip out[1..3], handled by head writers below).
    if (t < EMB_D) {
        const long idx = 1 + wbase + t;
        if (idx > 3) out[idx] += sum_w(t) * INVB;
    }
    // Bias-row patch (skip out[TOT], handled by tail writer below).
    if (t >= 96 && t < 96 + KTH) {
        const int  j   = t - 96;
        const long idx = 1 + bbase + j;
        if (idx < TOT_ELEMS) out[idx] -= sum_b(j) * INVB;
    }
    // Head: out[1..3] = src[0..2] (+patch if ctx == 0).
    if (t >= 68 && t < 71) {
        const int j = t - 68;
        float v = __ldg(emb + j);
        if (ctx == 0) v += sum_w(j) * INVB;
        out[1 + j] = v;
    }
    // Tail: out[TOT] = src[TOT-1] (-patch if ctx == WORDS-1).
    if (t == 72) {
        float v = __ldg(bia + B_ELEMS - 1);
        if (ctx == WORDS - 1) v -= sum_b(KTH - 1) * INVB;
        out[TOT_ELEMS] = v;
    }
}

extern "C" void kernel_launch(void* const* d_in, const int* in_sizes, int n_in,
                              void* d_out, int out_size) {
    const float* in_embed = (const float*)d_in[0];
    const float* in_bias  = (const float*)d_in[1];
    const int*   ctx_id   = (const int*)d_in[2];
    const int*   tgt      = (const int*)d_in[3];
    const int*   lab      = (const int*)d_in[4];
    float* out = (float*)d_out;
    (void)n_in; (void)out_size; (void)in_sizes;

    const long nchunks = K_CH - 1;                       // chunks 1..K_CH-1
    const int  blocks  = (int)((nchunks + CPB - 1) / CPB);
    prank_main_kernel<<<blocks, TPB>>>(in_embed, in_bias, ctx_id, tgt, lab, out);
    prank_patch_kernel<<<1, 128>>>(in_embed, in_bias, ctx_id, out);
}

// round 8
// speedup vs baseline: 1.3228x; 1.1103x over previous
#include <cuda_runtime.h>
#include <cstddef>

#define WORDS   1000000
#define EMB_D   64
#define KTH     4
#define BATCH   8192

#define E_ELEMS   ((long)WORDS * EMB_D)          // 64,000,000
#define B_ELEMS   ((long)WORDS * KTH)            // 4,000,000
#define TOT_ELEMS (E_ELEMS + B_ELEMS)            // 68,000,000
#define K_CH      (TOT_ELEMS / 4)                // 17,000,000 float4 chunks
#define E_CH      (E_ELEMS / 4)                  // 16,000,000
#define RB        128                            // reduce blocks
#define INVB      (1.0f / (float)BATCH)

#define TPB     256
#define UNROLL  4
#define CPB     (TPB * UNROLL)                   // 1024 chunks per block

// Per-block partials (fully overwritten each launch -> graph-replay safe).
__device__ float g_pw[RB][EMB_D];
__device__ float g_pb[RB][KTH];
__device__ int   g_pc[RB];

// ---------------------------------------------------------------------------
// Helpers
// ---------------------------------------------------------------------------
__device__ __forceinline__ float load_src(long s,
                                          const float* __restrict__ emb,
                                          const float* __restrict__ bia) {
    return (s < E_ELEMS) ? __ldg(emb + s) : __ldg(bia + (s - E_ELEMS));
}

__device__ __forceinline__ float4 load_chunk_cs(long k,
                                                const float* __restrict__ emb,
                                                const float* __restrict__ bia) {
    const float4* p = (k < E_CH)
        ? (reinterpret_cast<const float4*>(emb) + k)
        : (reinterpret_cast<const float4*>(bia) + (k - E_CH));
    return __ldcs(p);
}

// ---------------------------------------------------------------------------
// Reduce body (runs inside copy kernel for blockIdx.x < RB)
// ---------------------------------------------------------------------------
__device__ void reduce_body(const float* __restrict__ embed,
                            const float* __restrict__ bias,
                            const int*   __restrict__ ctx_id,
                            const int*   __restrict__ tgt,
                            const int*   __restrict__ lab) {
    __shared__ float s_ctx[EMB_D];
    __shared__ float s_bias[KTH];
    __shared__ float s_w[8][EMB_D];
    __shared__ float s_b[8][KTH];
    __shared__ int   s_c[8];

    const int tid = threadIdx.x;
    const int ctx = __ldg(ctx_id);
    if (tid < EMB_D) s_ctx[tid]  = __ldg(embed + (size_t)ctx * EMB_D + tid);
    if (tid < KTH)   s_bias[tid] = __ldg(bias  + (size_t)ctx * KTH + tid);
    __syncthreads();

    const int warp  = tid >> 5;
    const int lane  = tid & 31;
    const int gwarp = blockIdx.x * 8 + warp;     // 1024 warps total
    const int twarps = RB * 8;

    const float2 c2 = reinterpret_cast<const float2*>(s_ctx)[lane];

    float wx = 0.0f, wy = 0.0f;
    float b0 = 0.0f, b1 = 0.0f, b2 = 0.0f, b3 = 0.0f;
    int corr = 0;

    for (int b = gwarp; b < BATCH; b += twarps) {
        const int t = __ldg(tgt + b);
        const float2 e2 =
            reinterpret_cast<const float2*>(embed + (size_t)t * EMB_D)[lane];
        float p = e2.x * c2.x + e2.y * c2.y;
        #pragma unroll
        for (int o = 16; o; o >>= 1) p += __shfl_xor_sync(0xffffffffu, p, o);
        const float dot = p;

        const int   L    = __ldg(lab + b);
        const float labf = (float)L;

        float taurow = 0.0f;
        int   plabel = KTH + 1;
        float tj[KTH];
        #pragma unroll
        for (int j = KTH - 1; j >= 0; j--) {
            const float db = dot - s_bias[j];
            if (db <= 0.0f) plabel = j + 1;
            const float yt  = (j < L) ? 1.0f : -1.0f;
            const float tau = (db * yt > 0.0f) ? 0.0f : labf;
            tj[j] = tau;
            taurow += tau;
        }
        if (lane == 0) {
            b0 += tj[0]; b1 += tj[1]; b2 += tj[2]; b3 += tj[3];
            if (plabel == L) corr++;
        }
        wx += taurow * e2.x;
        wy += taurow * e2.y;
    }

    s_w[warp][2 * lane]     = wx;
    s_w[warp][2 * lane + 1] = wy;
    if (lane == 0) {
        s_b[warp][0] = b0; s_b[warp][1] = b1; s_b[warp][2] = b2; s_b[warp][3] = b3;
        s_c[warp] = corr;
    }
    __syncthreads();

    if (tid < EMB_D) {
        float s = 0.0f;
        #pragma unroll
        for (int w = 0; w < 8; w++) s += s_w[w][tid];
        g_pw[blockIdx.x][tid] = s;
    }
    if (tid < KTH) {
        float s = 0.0f;
        #pragma unroll
        for (int w = 0; w < 8; w++) s += s_b[w][tid];
        g_pb[blockIdx.x][tid] = s;
    }
    if (tid == 0) {
        int s = 0;
        #pragma unroll
        for (int w = 0; w < 8; w++) s += s_c[w];
        g_pc[blockIdx.x] = s;
    }
}

// ---------------------------------------------------------------------------
// Fused kernel: blocks 0..RB-1 reduce first, then all blocks stream-copy.
// Pure shifted copy: out[4k .. 4k+3] = src[4k-1 .. 4k+2] for chunks k.
// Coalesced: thread tid of a block handles chunks base + i*TPB + tid.
// ---------------------------------------------------------------------------
__global__ void __launch_bounds__(TPB)
prank_main_kernel(const float* __restrict__ emb,
                  const float* __restrict__ bia,
                  const int*   __restrict__ ctx_id,
                  const int*   __restrict__ tgt,
                  const int*   __restrict__ lab,
                  float* __restrict__ out) {
    if (blockIdx.x < RB)
        reduce_body(emb, bia, ctx_id, tgt, lab);

    const long base = (long)blockIdx.x * CPB + 1;
    const int  tid  = threadIdx.x;
    const int  lane = tid & 31;

    long   k[UNROLL];
    float4 B[UNROLL];
    float  prev[UNROLL];

    #pragma unroll
    for (int i = 0; i < UNROLL; i++) {
        long kk = base + (long)i * TPB + tid;
        if (kk >= K_CH) kk = K_CH - 1;            // clamp keeps warp converged
        k[i] = kk;
        B[i] = load_chunk_cs(kk, emb, bia);
    }

    #pragma unroll
    for (int i = 0; i < UNROLL; i++) {
        prev[i] = __shfl_up_sync(0xffffffffu, B[i].w, 1);
        if (lane == 0) prev[i] = load_src(4 * k[i] - 1, emb, bia);
    }

    #pragma unroll
    for (int i = 0; i < UNROLL; i++) {
        const long kk = base + (long)i * TPB + tid;
        if (kk < K_CH) {
            __stcs(reinterpret_cast<float4*>(out) + kk,
                   make_float4(prev[i], B[i].x, B[i].y, B[i].z));
        }
    }
}

// ---------------------------------------------------------------------------
// Patch: cooperative coalesced reduction of per-block partials, then write
// acc + context embed row + context bias row + head (out[1..3]) + tail.
// All writer sets are disjoint.
// ---------------------------------------------------------------------------
__global__ void __launch_bounds__(256)
prank_patch_kernel(const float* __restrict__ emb,
                   const float* __restrict__ bia,
                   const int*   __restrict__ ctx_id,
                   float* __restrict__ out) {
    __shared__ float t_w[4][EMB_D];
    __shared__ float s_w[EMB_D];
    __shared__ float s_pb[4][KTH];
    __shared__ int   s_pc[4];
    __shared__ float s_b[KTH];
    __shared__ int   s_c;

    const int tid  = threadIdx.x;
    const int lane = tid & 31;
    const int warp = tid >> 5;

    // --- g_pw: 128x64. group g = tid>>6 handles rows g, g+4, ... (coalesced) ---
    {
        const int g = tid >> 6;        // 0..3
        const int c = tid & 63;        // column
        float acc = 0.0f;
        #pragma unroll
        for (int i = 0; i < RB / 4; i++)
            acc += g_pw[g + 4 * i][c];
        t_w[g][c] = acc;
    }

    // --- g_pb: 128x4. threads 0..127 load one float4 row, shuffle-reduce ---
    if (tid < 128) {
        float4 v = reinterpret_cast<const float4*>(g_pb)[tid];
        int c = g_pc[tid];
        #pragma unroll
        for (int o = 16; o; o >>= 1) {
            v.x += __shfl_xor_sync(0xffffffffu, v.x, o);
            v.y += __shfl_xor_sync(0xffffffffu, v.y, o);
            v.z += __shfl_xor_sync(0xffffffffu, v.z, o);
            v.w += __shfl_xor_sync(0xffffffffu, v.w, o);
            c   += __shfl_xor_sync(0xffffffffu, c, o);
        }
        if (lane == 0) {
            s_pb[warp][0] = v.x; s_pb[warp][1] = v.y;
            s_pb[warp][2] = v.z; s_pb[warp][3] = v.w;
            s_pc[warp] = c;
        }
    }
    __syncthreads();

    if (tid < EMB_D)
        s_w[tid] = t_w[0][tid] + t_w[1][tid] + t_w[2][tid] + t_w[3][tid];
    if (tid >= 64 && tid < 64 + KTH) {
        const int j = tid - 64;
        s_b[j] = s_pb[0][j] + s_pb[1][j] + s_pb[2][j] + s_pb[3][j];
    }
    if (tid == 128)
        s_c = s_pc[0] + s_pc[1] + s_pc[2] + s_pc[3];
    __syncthreads();

    const int  ctx   = __ldg(ctx_id);
    const long wbase = (long)ctx * EMB_D;
    const long bbase = E_ELEMS + (long)ctx * KTH;

    // Accuracy scalar.
    if (tid == 128) out[0] = (float)s_c * INVB;

    // Context embed row: out[1+wbase+t] = emb + update (covers head if ctx==0).
    if (tid < EMB_D)
        out[1 + wbase + tid] = __ldg(emb + wbase + tid) + s_w[tid] * INVB;

    // Context bias row: covers tail if ctx == WORDS-1.
    if (tid >= 64 && tid < 64 + KTH) {
        const int j = tid - 64;
        out[1 + bbase + j] = __ldg(bia + (long)ctx * KTH + j) - s_b[j] * INVB;
    }

    // Head out[1..3]: copy never writes chunk 0; only if not covered by ctx row.
    if (tid >= 129 && tid < 132 && ctx != 0) {
        const int j = tid - 129;
        out[1 + j] = __ldg(emb + j);
    }
    // Tail out[TOT]: only if not covered by ctx bias row.
    if (tid == 132 && ctx != WORDS - 1)
        out[TOT_ELEMS] = __ldg(bia + B_ELEMS - 1);
}

extern "C" void kernel_launch(void* const* d_in, const int* in_sizes, int n_in,
                              void* d_out, int out_size) {
    const float* in_embed = (const float*)d_in[0];
    const float* in_bias  = (const float*)d_in[1];
    const int*   ctx_id   = (const int*)d_in[2];
    const int*   tgt      = (const int*)d_in[3];
    const int*   lab      = (const int*)d_in[4];
    float* out = (float*)d_out;
    (void)n_in; (void)out_size; (void)in_sizes;

    const long nchunks = K_CH - 1;                       // chunks 1..K_CH-1
    const int  blocks  = (int)((nchunks + CPB - 1) / CPB);
    prank_main_kernel<<<blocks, TPB>>>(in_embed, in_bias, ctx_id, tgt, lab, out);
    prank_patch_kernel<<<1, 256>>>(in_embed, in_bias, ctx_id, out);
}